// round 7
// baseline (speedup 1.0000x reference)
#include <cuda_runtime.h>
#include <stdint.h>

#define CAP4  2048     // float4 candidate slots (8192 floats, 32KB)
#define CAP2  2048     // stage-2 Y-candidates (Y > -1)
#define MAX_ROWS 16384

__device__ float    g_row_loss[MAX_ROWS];
__device__ unsigned g_done = 0;

__device__ __forceinline__ float warpMax(float v) {
    #pragma unroll
    for (int o = 16; o; o >>= 1) v = fmaxf(v, __shfl_xor_sync(0xffffffffu, v, o));
    return v;
}
__device__ __forceinline__ float warpSum(float v) {
    #pragma unroll
    for (int o = 16; o; o >>= 1) v += __shfl_xor_sync(0xffffffffu, v, o);
    return v;
}

__global__ __launch_bounds__(512, 4)
void entmax15_loss_kernel(const float* __restrict__ input,
                          const void* __restrict__ target,
                          int n, int d, float* __restrict__ out) {
    __shared__ float4 cand4[CAP4];
    __shared__ float  candY[CAP2];
    __shared__ float  shA[16], shB[16], shC[16];
    __shared__ float  s_red0, s_red1;
    __shared__ int    s_cnt4, s_cnt2, s_tg32, s_last;
    __shared__ float  s_tau, s_xt;

    const int tid  = threadIdx.x;
    const int lane = tid & 31;
    const int wid  = tid >> 5;
    const int bd   = blockDim.x;
    const int nw   = bd >> 5;
    const unsigned FULL = 0xffffffffu;

    const float* in_row = input + (size_t)blockIdx.x * (size_t)d;
    const bool al = ((((uintptr_t)in_row) & 15) == 0) && ((d & 3) == 0);

    if (tid == 0) { s_cnt4 = 0; s_cnt2 = 0; }

    // ---- dtype probe (warp 0): int32 buffer read as int64 leaves [0,d) ----
    if (wid == 0) {
        int lim = n >> 1; if (lim > 32) lim = 32;
        bool bad = false;
        if (lane < lim) {
            long long v = ((const long long*)target)[lane];
            bad = (v < 0 || v >= (long long)d);
        }
        unsigned mk = __ballot_sync(FULL, bad);
        if (lane == 0) s_tg32 = (mk != 0);
    }

    // ---- Sample max over first min(d,4096) elements ----
    // Loss is shift-invariant => any reference R <= true max works exactly.
    const int slen = (d < 4096) ? d : 4096;
    float smax = -INFINITY;
    if (al) {
        const float4* in4 = (const float4*)in_row;
        const int s4 = slen >> 2;
        for (int i = tid; i < s4; i += bd) {
            float4 v = in4[i];
            smax = fmaxf(fmaxf(v.x, v.y), fmaxf(fmaxf(v.z, v.w), smax));
        }
    } else {
        for (int i = tid; i < slen; i += bd) smax = fmaxf(smax, in_row[i]);
    }
    smax = warpMax(smax);
    if (lane == 0) shA[wid] = smax;
    __syncthreads();
    if (tid < 32) {
        float m = (tid < nw) ? shA[tid] : -INFINITY;
        m = warpMax(m);
        if (tid == 0) s_red0 = m;
    }
    __syncthreads();
    const float R   = 0.5f * s_red0;     // reference point (Y = x/2 - R)
    const float thr = s_red0 - 2.0f;     // support superset: x > thr  (<=> Y > -1)

    if (tid == 0) {
        long long tg = s_tg32 ? (long long)(((const int*)target)[blockIdx.x])
                              : ((const long long*)target)[blockIdx.x];
        if (tg < 0) tg = 0;
        if (tg >= d) tg = d - 1;
        s_xt = in_row[tg];
    }
    __syncthreads();

    // ---- Streaming pass: one compare + one ballot per float4; hit lanes
    //      dump the WHOLE float4 (junk below thr is inert: Y <= -1 <= tau). ----
    if (al) {
        const float4* in4 = (const float4*)in_row;
        const int d4   = d >> 2;
        const int full = d4 / bd;
        #pragma unroll 4
        for (int k = 0; k < full; ++k) {
            int i = tid + k * bd;
            float4 v = in4[i];
            float gm = fmaxf(fmaxf(v.x, v.y), fmaxf(v.z, v.w));
            unsigned m = __ballot_sync(FULL, gm > thr);
            if (m) {
                int base = 0;
                if (lane == 0) base = atomicAdd(&s_cnt4, __popc(m));
                base = __shfl_sync(FULL, base, 0);
                if (gm > thr) {
                    int id = base + __popc(m & ((1u << lane) - 1u));
                    if (id < CAP4) cand4[id] = v;   // one STS.128
                }
            }
        }
        // masked tail (single iteration)
        {
            int i = tid + full * bd;
            float4 v = make_float4(-INFINITY, -INFINITY, -INFINITY, -INFINITY);
            if (i < d4) v = in4[i];
            float gm = fmaxf(fmaxf(v.x, v.y), fmaxf(v.z, v.w));
            unsigned m = __ballot_sync(FULL, gm > thr);
            if (m) {
                int base = 0;
                if (lane == 0) base = atomicAdd(&s_cnt4, __popc(m));
                base = __shfl_sync(FULL, base, 0);
                if (gm > thr) {
                    int id = base + __popc(m & ((1u << lane) - 1u));
                    if (id < CAP4) cand4[id] = v;
                }
            }
        }
    } else {
        // Unaligned/odd-d: force the exact full-row fallback below.
        if (tid == 0) s_cnt4 = CAP4 + 1;
    }
    __syncthreads();
    const int  count4 = s_cnt4;
    const bool fit = (count4 <= CAP4);           // block-uniform

    // ---- Stage-2: filter Y = x/2 - R > -1 exactly into candY ----
    const float* candf = (const float*)cand4;
    const int    nf    = count4 * 4;
    if (fit) {
        const int iters = (nf + bd - 1) / bd;
        for (int k = 0; k < iters; ++k) {
            int i = tid + k * bd;
            float y = (i < nf) ? fmaf(0.5f, candf[i], -R) : -2.0f;
            unsigned m = __ballot_sync(FULL, y > -1.0f);
            if (m) {
                int base = 0;
                if (lane == 0) base = atomicAdd(&s_cnt2, __popc(m));
                base = __shfl_sync(FULL, base, 0);
                if (y > -1.0f) {
                    int id = base + __popc(m & ((1u << lane) - 1u));
                    if (id < CAP2) candY[id] = y;
                }
            }
        }
    }
    __syncthreads();
    const int  count2 = s_cnt2;
    const bool fit2 = fit && (count2 <= CAP2);

    // ---- Newton on f(tau) = sum max(Y-tau,0)^2 = 1, root in [-1, Ymax) ----
    // f convex decreasing; from tau=-1 (f(-1)>=1) convergence is monotone.
    float tau;
    if (fit) {
        if (wid == 0) {
            float tl = -1.0f;
            #pragma unroll 1
            for (int it = 0; it < 20; ++it) {
                float s1 = 0.f, s2 = 0.f;
                if (fit2) {
                    for (int i = lane; i < count2; i += 32) {
                        float t = candY[i] - tl;
                        if (t > 0.f) { s1 += t; s2 = fmaf(t, t, s2); }
                    }
                } else {
                    for (int i = lane; i < nf; i += 32) {
                        float t = fmaf(0.5f, candf[i], -R) - tl;
                        if (t > 0.f) { s1 += t; s2 = fmaf(t, t, s2); }
                    }
                }
                s1 = warpSum(s1); s2 = warpSum(s2);
                float corr = (s2 - 1.0f) / (2.0f * fmaxf(s1, 1e-30f));
                tl += corr;
                if (fabsf(corr) < 1e-8f) break;
            }
            if (lane == 0) s_tau = tl;
        }
        __syncthreads();
        tau = s_tau;
    } else {
        // Rare fallback: block-wide Newton over the full row (L2 reads).
        tau = -1.0f;
        for (int it = 0; it < 24; ++it) {
            float s1 = 0.f, s2 = 0.f;
            for (int i = tid; i < d; i += bd) {
                float t = fmaf(0.5f, in_row[i], -R) - tau;
                if (t > 0.f) { s1 += t; s2 = fmaf(t, t, s2); }
            }
            s1 = warpSum(s1); s2 = warpSum(s2);
            if (lane == 0) { shA[wid] = s1; shB[wid] = s2; }
            __syncthreads();
            if (tid < 32) {
                float a = (tid < nw) ? shA[tid] : 0.f;
                float b = (tid < nw) ? shB[tid] : 0.f;
                a = warpSum(a); b = warpSum(b);
                if (tid == 0) { s_red0 = a; s_red1 = b; }
            }
            __syncthreads();
            tau += (s_red1 - 1.0f) / (2.0f * fmaxf(s_red0, 1e-30f));
            __syncthreads();
        }
    }

    // ---- Epilogue: loss = (1 - sum t^3)*4/3 + 2*sum t^2*Y + 2*R*sum t^2 - x_t ----
    float t3 = 0.f, py = 0.f, p2 = 0.f;
    if (fit2) {
        for (int i = tid; i < count2; i += bd) {
            float y = candY[i];
            float t = y - tau;
            if (t > 0.f) { float p = t * t; t3 = fmaf(p, t, t3); py = fmaf(p, y, py); p2 += p; }
        }
    } else if (fit) {
        for (int i = tid; i < nf; i += bd) {
            float y = fmaf(0.5f, candf[i], -R);
            float t = y - tau;
            if (t > 0.f) { float p = t * t; t3 = fmaf(p, t, t3); py = fmaf(p, y, py); p2 += p; }
        }
    } else {
        for (int i = tid; i < d; i += bd) {
            float y = fmaf(0.5f, in_row[i], -R);
            float t = y - tau;
            if (t > 0.f) { float p = t * t; t3 = fmaf(p, t, t3); py = fmaf(p, y, py); p2 += p; }
        }
    }
    t3 = warpSum(t3); py = warpSum(py); p2 = warpSum(p2);
    if (lane == 0) { shA[wid] = t3; shB[wid] = py; shC[wid] = p2; }
    __syncthreads();
    if (tid < 32) {
        float a = (tid < nw) ? shA[tid] : 0.f;
        float b = (tid < nw) ? shB[tid] : 0.f;
        float c = (tid < nw) ? shC[tid] : 0.f;
        a = warpSum(a); b = warpSum(b); c = warpSum(c);
        if (tid == 0) {
            float omega = (1.0f - a) * (4.0f / 3.0f);
            g_row_loss[blockIdx.x] = omega + 2.0f * b + 2.0f * R * c - s_xt;
        }
    }
    __syncthreads();

    // ---- Deterministic in-kernel mean: last block reduces ----
    if (tid == 0) {
        __threadfence();
        unsigned prev = atomicAdd(&g_done, 1u);
        s_last = (prev == (unsigned)(n - 1));
    }
    __syncthreads();
    if (s_last) {
        float a = 0.f;
        for (int i = tid; i < n; i += bd) a += g_row_loss[i];  // fixed order
        a = warpSum(a);
        if (lane == 0) shA[wid] = a;
        __syncthreads();
        if (tid < 32) {
            float v = (tid < nw) ? shA[tid] : 0.f;
            v = warpSum(v);
            if (tid == 0) { out[0] = v / (float)n; g_done = 0u; }
        }
    }
}

extern "C" void kernel_launch(void* const* d_in, const int* in_sizes, int n_in,
                              void* d_out, int out_size) {
    const int i_in = (in_sizes[0] >= in_sizes[1]) ? 0 : 1;
    const int i_tg = 1 - i_in;
    const float* input  = (const float*)d_in[i_in];
    const void*  target = d_in[i_tg];
    const int n = in_sizes[i_tg];
    const int d = in_sizes[i_in] / n;

    entmax15_loss_kernel<<<n, 512>>>(input, target, n, d, (float*)d_out);
}

// round 11
// speedup vs baseline: 3.2782x; 3.2782x over previous
#include <cuda_runtime.h>
#include <stdint.h>

#define NW      16      // warps per block (512 threads)
#define CAPW4   160     // float4 slots per warp segment
#define MAX_ROWS 16384

__device__ float    g_row_loss[MAX_ROWS];
__device__ unsigned g_done = 0;

__device__ __forceinline__ float warpMax(float v) {
    #pragma unroll
    for (int o = 16; o; o >>= 1) v = fmaxf(v, __shfl_xor_sync(0xffffffffu, v, o));
    return v;
}
__device__ __forceinline__ float warpSum(float v) {
    #pragma unroll
    for (int o = 16; o; o >>= 1) v += __shfl_xor_sync(0xffffffffu, v, o);
    return v;
}

__global__ __launch_bounds__(512, 4)
void entmax15_loss_kernel(const float* __restrict__ input,
                          const void* __restrict__ target,
                          int n, int d, float* __restrict__ out) {
    __shared__ float4 seg[NW][CAPW4];          // 40 KB
    __shared__ int    segcnt[NW];
    __shared__ float  shA[NW], shB[NW], shC[NW];
    __shared__ float  s_red0, s_red1;
    __shared__ int    s_tg32, s_last;
    __shared__ float  s_xt;

    const int tid  = threadIdx.x;
    const int lane = tid & 31;
    const int wid  = tid >> 5;
    const int bd   = blockDim.x;
    const unsigned FULL = 0xffffffffu;
    const unsigned LT   = (1u << lane) - 1u;

    const float* in_row = input + (size_t)blockIdx.x * (size_t)d;
    const bool al = ((((uintptr_t)in_row) & 15) == 0) && ((d & 3) == 0);

    // ---- dtype probe (warp 0): int32 buffer read as int64 leaves [0,d) ----
    if (wid == 0) {
        int lim = n >> 1; if (lim > 32) lim = 32;
        bool bad = false;
        if (lane < lim) {
            long long v = ((const long long*)target)[lane];
            bad = (v < 0 || v >= (long long)d);
        }
        unsigned mk = __ballot_sync(FULL, bad);
        if (lane == 0) s_tg32 = (mk != 0);
    }

    // ---- Sample max over first min(d,4096) elements ----
    const int slen = (d < 4096) ? d : 4096;
    float smax = -INFINITY;
    if (al) {
        const float4* in4 = (const float4*)in_row;
        const int s4 = slen >> 2;
        for (int i = tid; i < s4; i += bd) {
            float4 v = in4[i];
            smax = fmaxf(fmaxf(v.x, v.y), fmaxf(fmaxf(v.z, v.w), smax));
        }
    } else {
        for (int i = tid; i < slen; i += bd) smax = fmaxf(smax, in_row[i]);
    }
    smax = warpMax(smax);
    if (lane == 0) shA[wid] = smax;
    __syncthreads();
    if (tid < 32) {
        float m = (tid < NW) ? shA[tid] : -INFINITY;
        m = warpMax(m);
        if (tid == 0) s_red0 = m;
    }
    __syncthreads();
    const float thr0 = s_red0 - 2.0f;   // valid collect threshold: smax <= true max
    const float R_fb = 0.5f * s_red0;   // fallback reference (shift-invariant loss)

    if (tid == 0) {
        long long tg = s_tg32 ? (long long)(((const int*)target)[blockIdx.x])
                              : ((const long long*)target)[blockIdx.x];
        if (tg < 0) tg = 0;
        if (tg >= d) tg = d - 1;
        s_xt = in_row[tg];
    }
    __syncthreads();

    // ---- Streaming pass: warp-private compaction, no atomics ----
    // Per visit: LDG.128 + 4 FMAX + SETP + BALLOT (+ popc/IADD/STS on hit).
    float vmax = -INFINITY;
    int   wcount = 0;
    if (al) {
        const float4* in4 = (const float4*)in_row;
        const int d4 = d >> 2;
        const int iters = (d4 + bd - 1) / bd;
        for (int k = 0; k < iters; ++k) {
            int i = tid + k * bd;
            float4 v = make_float4(-INFINITY, -INFINITY, -INFINITY, -INFINITY);
            if (i < d4) v = in4[i];
            float gm = fmaxf(fmaxf(v.x, v.y), fmaxf(v.z, v.w));
            vmax = fmaxf(vmax, gm);
            bool take = (gm > thr0);
            unsigned m = __ballot_sync(FULL, take);
            if (m) {
                if (take) {
                    int id = wcount + __popc(m & LT);
                    if (id < CAPW4) seg[wid][id] = v;    // one STS.128
                }
                wcount += __popc(m);
            }
        }
    } else {
        wcount = CAPW4 + 1;   // force exact fallback for odd shapes
    }
    if (lane == 0) segcnt[wid] = wcount;

    // True row max
    vmax = warpMax(vmax);
    if (lane == 0) shA[wid] = vmax;
    __syncthreads();
    if (tid < 32) {
        float m = (tid < NW) ? shA[tid] : -INFINITY;
        m = warpMax(m);
        if (tid == 0) s_red0 = m;
    }
    __syncthreads();
    const float Mx = al ? s_red0 : (2.0f * R_fb);   // true max (al path)
    const float R  = al ? (0.5f * Mx) : R_fb;       // Y = 0.5*x - R

    // ---- Overflow check (block-uniform) ----
    bool over = false;
    #pragma unroll
    for (int w = 0; w < NW; ++w) over = over || (segcnt[w] > CAPW4);

    // ---- Overflow recovery: ONE exact re-collect at thr* = Mx - 2 ----
    bool full_fallback = false;
    if (over) {
        if (al && (Mx - 2.0f > thr0)) {
            const float thr1 = Mx - 2.0f;   // exact support threshold
            __syncthreads();                // segments re-written below
            wcount = 0;
            const float4* in4 = (const float4*)in_row;
            const int d4 = d >> 2;
            const int iters = (d4 + bd - 1) / bd;
            for (int k = 0; k < iters; ++k) {
                int i = tid + k * bd;
                float4 v = make_float4(-INFINITY, -INFINITY, -INFINITY, -INFINITY);
                if (i < d4) v = in4[i];
                float gm = fmaxf(fmaxf(v.x, v.y), fmaxf(v.z, v.w));
                bool take = (gm > thr1);
                unsigned m = __ballot_sync(FULL, take);
                if (m) {
                    if (take) {
                        int id = wcount + __popc(m & LT);
                        if (id < CAPW4) seg[wid][id] = v;
                    }
                    wcount += __popc(m);
                }
            }
            if (lane == 0) segcnt[wid] = wcount;
            __syncthreads();
            bool over2 = false;
            #pragma unroll
            for (int w = 0; w < NW; ++w) over2 = over2 || (segcnt[w] > CAPW4);
            full_fallback = over2;
        } else {
            full_fallback = true;
        }
    }
    __syncthreads();

    // ---- Newton: f(tau) = sum max(0.5*x - R - tau, 0)^2 = 1, root in [-1, Ymax] ----
    float tau = -1.0f;
    if (!full_fallback) {
        const float* sf   = (const float*)seg[wid];
        const int    nf_w = ((segcnt[wid] < CAPW4) ? segcnt[wid] : CAPW4) * 4;
        #pragma unroll 1
        for (int it = 0; it < 16; ++it) {
            float s1 = 0.f, s2 = 0.f;
            for (int j = lane; j < nf_w; j += 32) {
                float t = fmaf(0.5f, sf[j], -R) - tau;
                if (t > 0.f) { s1 += t; s2 = fmaf(t, t, s2); }
            }
            s1 = warpSum(s1); s2 = warpSum(s2);
            if (lane == 0) { shA[wid] = s1; shB[wid] = s2; }
            __syncthreads();
            if (tid < 32) {
                float a = (tid < NW) ? shA[tid] : 0.f;
                float b = (tid < NW) ? shB[tid] : 0.f;
                a = warpSum(a); b = warpSum(b);
                if (tid == 0) { s_red0 = a; s_red1 = b; }
            }
            __syncthreads();
            float corr = (s_red1 - 1.0f) / (2.0f * fmaxf(s_red0, 1e-30f));
            tau += corr;
            if (fabsf(corr) < 1e-8f) break;   // block-uniform
            __syncthreads();
        }
    } else {
        // Last-resort: block-wide Newton over the full row (L2 reads).
        #pragma unroll 1
        for (int it = 0; it < 24; ++it) {
            float s1 = 0.f, s2 = 0.f;
            for (int i = tid; i < d; i += bd) {
                float t = fmaf(0.5f, in_row[i], -R) - tau;
                if (t > 0.f) { s1 += t; s2 = fmaf(t, t, s2); }
            }
            s1 = warpSum(s1); s2 = warpSum(s2);
            if (lane == 0) { shA[wid] = s1; shB[wid] = s2; }
            __syncthreads();
            if (tid < 32) {
                float a = (tid < NW) ? shA[tid] : 0.f;
                float b = (tid < NW) ? shB[tid] : 0.f;
                a = warpSum(a); b = warpSum(b);
                if (tid == 0) { s_red0 = a; s_red1 = b; }
            }
            __syncthreads();
            tau += (s_red1 - 1.0f) / (2.0f * fmaxf(s_red0, 1e-30f));
            __syncthreads();
        }
    }
    __syncthreads();

    // ---- Epilogue: loss = (1 - sum t^3)*4/3 + 2*sum t^2*Y + 2*R*sum t^2 - x_t ----
    float t3 = 0.f, py = 0.f, p2 = 0.f;
    if (!full_fallback) {
        const float* sf   = (const float*)seg[wid];
        const int    nf_w = ((segcnt[wid] < CAPW4) ? segcnt[wid] : CAPW4) * 4;
        for (int j = lane; j < nf_w; j += 32) {
            float y = fmaf(0.5f, sf[j], -R);
            float t = y - tau;
            if (t > 0.f) { float p = t * t; t3 = fmaf(p, t, t3); py = fmaf(p, y, py); p2 += p; }
        }
    } else {
        for (int i = tid; i < d; i += bd) {
            float y = fmaf(0.5f, in_row[i], -R);
            float t = y - tau;
            if (t > 0.f) { float p = t * t; t3 = fmaf(p, t, t3); py = fmaf(p, y, py); p2 += p; }
        }
    }
    t3 = warpSum(t3); py = warpSum(py); p2 = warpSum(p2);
    if (lane == 0) { shA[wid] = t3; shB[wid] = py; shC[wid] = p2; }
    __syncthreads();
    if (tid < 32) {
        float a = (tid < NW) ? shA[tid] : 0.f;
        float b = (tid < NW) ? shB[tid] : 0.f;
        float c = (tid < NW) ? shC[tid] : 0.f;
        a = warpSum(a); b = warpSum(b); c = warpSum(c);
        if (tid == 0) {
            float omega = (1.0f - a) * (4.0f / 3.0f);
            g_row_loss[blockIdx.x] = omega + 2.0f * b + 2.0f * R * c - s_xt;
        }
    }
    __syncthreads();

    // ---- Deterministic in-kernel mean: last block reduces ----
    if (tid == 0) {
        __threadfence();
        unsigned prev = atomicAdd(&g_done, 1u);
        s_last = (prev == (unsigned)(n - 1));
    }
    __syncthreads();
    if (s_last) {
        float a = 0.f;
        for (int i = tid; i < n; i += bd) a += g_row_loss[i];  // fixed order
        a = warpSum(a);
        if (lane == 0) shA[wid] = a;
        __syncthreads();
        if (tid < 32) {
            float v = (tid < NW) ? shA[tid] : 0.f;
            v = warpSum(v);
            if (tid == 0) { out[0] = v / (float)n; g_done = 0u; }
        }
    }
}

extern "C" void kernel_launch(void* const* d_in, const int* in_sizes, int n_in,
                              void* d_out, int out_size) {
    const int i_in = (in_sizes[0] >= in_sizes[1]) ? 0 : 1;
    const int i_tg = 1 - i_in;
    const float* input  = (const float*)d_in[i_in];
    const void*  target = d_in[i_tg];
    const int n = in_sizes[i_tg];
    const int d = in_sizes[i_in] / n;

    entmax15_loss_kernel<<<n, 512>>>(input, target, n, d, (float*)d_out);
}